// round 1
// baseline (speedup 1.0000x reference)
#include <cuda_runtime.h>
#include <math.h>

#define NT   65536
#define NG   32
#define NPG  2048
#define NE   524288
#define HID  128

// ---------------- scratch (device globals; no allocation allowed) ------------
__device__ float g_bufA[(size_t)NT * HID];
__device__ float g_bufB[(size_t)NT * HID];
__device__ float g_agg [(size_t)NT * HID];
__device__ int   g_cnt[NT];
__device__ int   g_cursor[NT];
__device__ int   g_rowptr[NT + 1];
__device__ int   g_col[NE];
__device__ float g_prel[NT];
__device__ float g_base[NT];
__device__ float g_score[NT];
__device__ float g_nm1[NT];
__device__ float g_nm2[NT];
__device__ float g_gvec[NG * HID];

// ---------------- CSR build --------------------------------------------------
__global__ void k_zero_csr() {
    int i = blockIdx.x * blockDim.x + threadIdx.x;
    if (i < NT) { g_cnt[i] = 0; g_cursor[i] = 0; }
}

__global__ void k_hist(const int* __restrict__ dst) {
    int e = blockIdx.x * blockDim.x + threadIdx.x;
    if (e < NE) atomicAdd(&g_cnt[dst[e]], 1);
}

__global__ void k_scan() {
    __shared__ int sums[1024];
    int t = threadIdx.x;
    int base = t * 64;
    int s = 0;
    #pragma unroll 8
    for (int i = 0; i < 64; i++) s += g_cnt[base + i];
    sums[t] = s;
    __syncthreads();
    for (int off = 1; off < 1024; off <<= 1) {
        int v = (t >= off) ? sums[t - off] : 0;
        __syncthreads();
        sums[t] += v;
        __syncthreads();
    }
    int run = (t == 0) ? 0 : sums[t - 1];
    for (int i = 0; i < 64; i++) { g_rowptr[base + i] = run; run += g_cnt[base + i]; }
    if (t == 1023) g_rowptr[NT] = run;
}

__global__ void k_scatter(const int* __restrict__ src, const int* __restrict__ dst) {
    int e = blockIdx.x * blockDim.x + threadIdx.x;
    if (e >= NE) return;
    int d = dst[e];
    int pos = g_rowptr[d] + atomicAdd(&g_cursor[d], 1);
    g_col[pos] = src[e];
}

// ---------------- mean aggregation (warp per node, no atomics) ---------------
__global__ void k_agg_mean(const float* __restrict__ h, float* __restrict__ out,
                           const float* __restrict__ nm) {
    int n    = (blockIdx.x * blockDim.x + threadIdx.x) >> 5;
    int lane = threadIdx.x & 31;
    if (n >= NT) return;
    float4 acc = make_float4(0.f, 0.f, 0.f, 0.f);
    if (!(nm && nm[n] == 0.f)) {
        int r0 = g_rowptr[n], r1 = g_rowptr[n + 1];
        int cnt = 0;
        for (int j = r0; j < r1; j++) {
            int s = g_col[j];
            if (nm && nm[s] == 0.f) continue;
            cnt++;
            float4 v = *(const float4*)(h + (size_t)s * HID + lane * 4);
            acc.x += v.x; acc.y += v.y; acc.z += v.z; acc.w += v.w;
        }
        float inv = 1.f / (float)(cnt > 0 ? cnt : 1);
        acc.x *= inv; acc.y *= inv; acc.z *= inv; acc.w *= inv;
    }
    *(float4*)(out + (size_t)n * HID + lane * 4) = acc;
}

// ---------------- fused dual GEMM: out = relu(A1@W1 + A2@W2 + b) * nm --------
// 128x128 tile, K = 128 + 128. 256 threads, each 8x8 micro-tile.
__global__ __launch_bounds__(256) void k_gemm_dual(
    const float* __restrict__ A1, const float* __restrict__ W1,
    const float* __restrict__ A2, const float* __restrict__ W2,
    const float* __restrict__ bias, const float* __restrict__ nm,
    float* __restrict__ out)
{
    __shared__ float As[16][128];
    __shared__ float Bs[16][128];
    int tid = threadIdx.x;
    int r0 = blockIdx.x * 128;
    int ty = tid >> 4, tx = tid & 15;
    float acc[8][8];
    #pragma unroll
    for (int i = 0; i < 8; i++)
        #pragma unroll
        for (int j = 0; j < 8; j++) acc[i][j] = 0.f;

    for (int phase = 0; phase < 16; phase++) {
        const float* A = (phase < 8) ? A1 : A2;
        const float* W = (phase < 8) ? W1 : W2;
        int kk = (phase & 7) * 16;
        #pragma unroll
        for (int i = 0; i < 2; i++) {
            int v = tid + i * 256;
            int row = v >> 2;
            int c4  = v & 3;
            float4 a = *(const float4*)(A + (size_t)(r0 + row) * 128 + kk + c4 * 4);
            As[c4 * 4 + 0][row] = a.x;
            As[c4 * 4 + 1][row] = a.y;
            As[c4 * 4 + 2][row] = a.z;
            As[c4 * 4 + 3][row] = a.w;
            int k  = v >> 5;
            int n4 = v & 31;
            *(float4*)(&Bs[k][n4 * 4]) = *(const float4*)(W + (size_t)(kk + k) * 128 + n4 * 4);
        }
        __syncthreads();
        #pragma unroll
        for (int k = 0; k < 16; k++) {
            float a[8], b[8];
            #pragma unroll
            for (int i = 0; i < 8; i++) a[i] = As[k][ty * 8 + i];
            #pragma unroll
            for (int j = 0; j < 8; j++) b[j] = Bs[k][tx + j * 16];
            #pragma unroll
            for (int i = 0; i < 8; i++)
                #pragma unroll
                for (int j = 0; j < 8; j++)
                    acc[i][j] = fmaf(a[i], b[j], acc[i][j]);
        }
        __syncthreads();
    }
    float nmv[8];
    #pragma unroll
    for (int i = 0; i < 8; i++) nmv[i] = nm ? nm[r0 + ty * 8 + i] : 1.f;
    #pragma unroll
    for (int i = 0; i < 8; i++) {
        int row = r0 + ty * 8 + i;
        #pragma unroll
        for (int j = 0; j < 8; j++) {
            int cc = tx + j * 16;
            float v = fmaxf(acc[i][j] + bias[cc], 0.f) * nmv[i];
            out[(size_t)row * 128 + cc] = v;
        }
    }
}

// ---------------- pooling: per-node score GEMVs -------------------------------
__global__ void k_node_scores(const float* __restrict__ h,
                              const float* __restrict__ Prel,
                              const float* __restrict__ Proot,
                              const float* __restrict__ prb) {
    int n    = (blockIdx.x * blockDim.x + threadIdx.x) >> 5;
    int lane = threadIdx.x & 31;
    if (n >= NT) return;
    float4 hv = *(const float4*)(h + (size_t)n * HID + lane * 4);
    float4 pr = *(const float4*)(Prel + lane * 4);
    float4 po = *(const float4*)(Proot + lane * 4);
    float s1 = hv.x * pr.x + hv.y * pr.y + hv.z * pr.z + hv.w * pr.w;
    float s2 = hv.x * po.x + hv.y * po.y + hv.z * po.z + hv.w * po.w;
    #pragma unroll
    for (int off = 16; off > 0; off >>= 1) {
        s1 += __shfl_down_sync(0xffffffffu, s1, off);
        s2 += __shfl_down_sync(0xffffffffu, s2, off);
    }
    if (lane == 0) { g_prel[n] = s1; g_base[n] = s2 + prb[0]; }
}

// score[n] = base[n] + sum_{in-edges} prel[src]   (scalar scatter, no mask
// needed: dead-node features are exact zeros so their prel is exactly 0)
__global__ void k_score_agg(const float* __restrict__ nm) {
    int n = blockIdx.x * blockDim.x + threadIdx.x;
    if (n >= NT) return;
    if (nm && nm[n] == 0.f) { g_score[n] = -1e30f; return; }
    float s = g_base[n];
    int r0 = g_rowptr[n], r1 = g_rowptr[n + 1];
    for (int j = r0; j < r1; j++) s += g_prel[g_col[j]];
    g_score[n] = s;
}

__global__ void k_zero_f(float* p, int n) {
    int i = blockIdx.x * blockDim.x + threadIdx.x;
    if (i < n) p[i] = 0.f;
}

// exact top-k per graph via bitonic sort of (score, index) keys in smem
__global__ __launch_bounds__(1024) void k_topk(float* __restrict__ nm_out, int k) {
    __shared__ unsigned long long keys[NPG];
    int g = blockIdx.x, t = threadIdx.x;
    for (int i = t; i < NPG; i += 1024) {
        float f = g_score[g * NPG + i];
        unsigned u = __float_as_uint(f);
        u = (u & 0x80000000u) ? ~u : (u | 0x80000000u);   // order-preserving map
        keys[i] = (((unsigned long long)u) << 32) | (unsigned)(0xFFFFFFFFu - i);
    }
    __syncthreads();
    for (int ksz = 2; ksz <= NPG; ksz <<= 1) {
        for (int j = ksz >> 1; j > 0; j >>= 1) {
            int i   = ((t & ~(j - 1)) << 1) | (t & (j - 1));
            int ixj = i | j;
            bool asc = ((i & ksz) == 0);
            unsigned long long a = keys[i], b = keys[ixj];
            if ((a > b) == asc) { keys[i] = b; keys[ixj] = a; }
            __syncthreads();
        }
    }
    for (int i = t; i < k; i += 1024) {
        unsigned long long key = keys[NPG - 1 - i];
        int idx = (int)(0xFFFFFFFFu - (unsigned)(key & 0xFFFFFFFFu));
        nm_out[g * NPG + idx] = 1.f;
    }
}

// h_out = h_in * tanh(score) * nm   (nm==0 forces exact zero row)
__global__ void k_hupdate(const float* __restrict__ hin, float* __restrict__ hout,
                          const float* __restrict__ nm) {
    int n    = (blockIdx.x * blockDim.x + threadIdx.x) >> 5;
    int lane = threadIdx.x & 31;
    if (n >= NT) return;
    float m = nm[n];
    float t = (m > 0.f) ? tanhf(g_score[n]) : 0.f;
    float4 v = *(const float4*)(hin + (size_t)n * HID + lane * 4);
    v.x *= t; v.y *= t; v.z *= t; v.w *= t;
    *(float4*)(hout + (size_t)n * HID + lane * 4) = v;
}

// ---------------- readout -----------------------------------------------------
__global__ void k_graph_reduce(const float* __restrict__ h) {
    int g = blockIdx.x, c = threadIdx.x;   // 128 threads per block
    const float* base = h + (size_t)g * NPG * HID;
    float s = 0.f;
    #pragma unroll 8
    for (int n = 0; n < NPG; n++) s += base[(size_t)n * HID + c];
    g_gvec[g * HID + c] = s * (1.f / 512.f);   // exactly k2=512 survivors/graph
}

__global__ __launch_bounds__(1024) void k_head(
    const float* __restrict__ W5, const float* __restrict__ b5,
    const float* __restrict__ W6, const float* __restrict__ b6,
    float* __restrict__ out)
{
    __shared__ float hid[NG][64];
    int w = threadIdx.x >> 5, lane = threadIdx.x & 31;
    for (int c = lane; c < 64; c += 32) {
        float s = b5[c];
        #pragma unroll 8
        for (int i = 0; i < HID; i++) s += g_gvec[w * HID + i] * W5[i * 64 + c];
        hid[w][c] = fmaxf(s, 0.f);
    }
    __syncwarp();
    if (lane == 0) {
        float l0 = b6[0], l1 = b6[1];
        #pragma unroll 8
        for (int i = 0; i < 64; i++) {
            float hv = hid[w][i];
            l0 += hv * W6[i * 2 + 0];
            l1 += hv * W6[i * 2 + 1];
        }
        float m = fmaxf(l0, l1);
        float lse = m + logf(expf(l0 - m) + expf(l1 - m));
        out[w * 2 + 0] = l0 - lse;
        out[w * 2 + 1] = l1 - lse;
    }
}

// ---------------- launch ------------------------------------------------------
extern "C" void kernel_launch(void* const* d_in, const int* in_sizes, int n_in,
                              void* d_out, int out_size) {
    (void)in_sizes; (void)n_in; (void)out_size;
    const float* x     = (const float*)d_in[0];
    const int*   ei    = (const int*)d_in[1];
    const int*   src   = ei;
    const int*   dst   = ei + NE;
    const float* Wl1 = (const float*)d_in[4],  *bl1 = (const float*)d_in[5],  *Wr1 = (const float*)d_in[6];
    const float* Wl2 = (const float*)d_in[7],  *bl2 = (const float*)d_in[8],  *Wr2 = (const float*)d_in[9];
    const float* Wl3 = (const float*)d_in[10], *bl3 = (const float*)d_in[11], *Wr3 = (const float*)d_in[12];
    const float* Wl4 = (const float*)d_in[13], *bl4 = (const float*)d_in[14], *Wr4 = (const float*)d_in[15];
    const float* Prel1 = (const float*)d_in[16], *prb1 = (const float*)d_in[17], *Proot1 = (const float*)d_in[18];
    const float* Prel2 = (const float*)d_in[19], *prb2 = (const float*)d_in[20], *Proot2 = (const float*)d_in[21];
    const float* W5 = (const float*)d_in[22], *b5 = (const float*)d_in[23];
    const float* W6 = (const float*)d_in[24], *b6 = (const float*)d_in[25];
    float* out = (float*)d_out;

    float *bufA, *bufB, *agg, *nm1, *nm2;
    cudaGetSymbolAddress((void**)&bufA, g_bufA);
    cudaGetSymbolAddress((void**)&bufB, g_bufB);
    cudaGetSymbolAddress((void**)&agg,  g_agg);
    cudaGetSymbolAddress((void**)&nm1,  g_nm1);
    cudaGetSymbolAddress((void**)&nm2,  g_nm2);

    const int AGG_GRID = (NT * 32) / 256;  // warp per node

    // CSR build (deterministic per launch; edge order within a row only
    // perturbs fp sum order, well under rel_err tolerance)
    k_zero_csr<<<NT / 256, 256>>>();
    k_hist<<<NE / 256, 256>>>(dst);
    k_scan<<<1, 1024>>>();
    k_scatter<<<NE / 256, 256>>>(src, dst);

    // SAGE 1: h1 = relu(mean_agg(x)@Wl1 + x@Wr1 + bl1)
    k_agg_mean<<<AGG_GRID, 256>>>(x, agg, nullptr);
    k_gemm_dual<<<NT / 128, 256>>>(agg, Wl1, x, Wr1, bl1, nullptr, bufA);
    // SAGE 2
    k_agg_mean<<<AGG_GRID, 256>>>(bufA, agg, nullptr);
    k_gemm_dual<<<NT / 128, 256>>>(agg, Wl2, bufA, Wr2, bl2, nullptr, bufB);

    // SAGPool 1 (k = 1024)
    k_node_scores<<<AGG_GRID, 256>>>(bufB, Prel1, Proot1, prb1);
    k_score_agg<<<NT / 256, 256>>>(nullptr);
    k_zero_f<<<NT / 256, 256>>>(nm1, NT);
    k_topk<<<NG, 1024>>>(nm1, 1024);
    k_hupdate<<<AGG_GRID, 256>>>(bufB, bufA, nm1);

    // SAGE 3 (edge mask == nm1[src]*nm1[dst])
    k_agg_mean<<<AGG_GRID, 256>>>(bufA, agg, nm1);
    k_gemm_dual<<<NT / 128, 256>>>(agg, Wl3, bufA, Wr3, bl3, nm1, bufB);
    // SAGE 4
    k_agg_mean<<<AGG_GRID, 256>>>(bufB, agg, nm1);
    k_gemm_dual<<<NT / 128, 256>>>(agg, Wl4, bufB, Wr4, bl4, nm1, bufA);

    // SAGPool 2 (k = 512)
    k_node_scores<<<AGG_GRID, 256>>>(bufA, Prel2, Proot2, prb2);
    k_score_agg<<<NT / 256, 256>>>(nm1);
    k_zero_f<<<NT / 256, 256>>>(nm2, NT);
    k_topk<<<NG, 1024>>>(nm2, 512);
    k_hupdate<<<AGG_GRID, 256>>>(bufA, bufB, nm2);

    // readout: global mean pool -> MLP -> log_softmax
    k_graph_reduce<<<NG, 128>>>(bufB);
    k_head<<<1, 1024>>>(W5, b5, W6, b6, out);
}